// round 11
// baseline (speedup 1.0000x reference)
#include <cuda_runtime.h>
#include <math.h>

#define N1C 50000
#define E1C 1000000
#define N2C 199
#define E2C 4000
#define MC (N1C + N2C)
#define FIN 128
#define BATCH 10
#define NPGC 5000
#define TOPK 50
#define LN_EPS 1e-5f

static inline int cdiv(int a, int b) { return (a + b - 1) / b; }

// ---------------- scratch ----------------
__device__ float d_z[MC * 128];
__device__ float d_r[MC * 128];
__device__ float d_h[MC * 128];
__device__ float d_o[MC * 64];
__device__ int d_cnt[MC];
__device__ int d_offs[MC + 1];
__device__ int d_cur[MC];
__device__ int d_csr[E1C + E2C];
__device__ int d_bsum[128];
__device__ unsigned long long d_codes[N1C];
__device__ int d_sel[BATCH * TOPK];
__device__ float d_feat[BATCH * TOPK * N2C];
__device__ float d_pre1[BATCH * 128];

// ---------------- f32x2 helpers ----------------
__device__ __forceinline__ unsigned long long dup2(float x) {
    unsigned long long r;
    asm("mov.b64 %0, {%1, %1};" : "=l"(r) : "r"(__float_as_uint(x)));
    return r;
}
__device__ __forceinline__ void ffma2(unsigned long long& d, unsigned long long a,
                                      unsigned long long b) {
    asm("fma.rn.f32x2 %0, %1, %2, %0;" : "+l"(d) : "l"(a), "l"(b));
}

// ---------------- CSR build ----------------
__global__ void zero_int_kernel(int* p, int n) {
    int i = blockIdx.x * blockDim.x + threadIdx.x;
    if (i < n) p[i] = 0;
}

__global__ void count2_kernel(const int* __restrict__ ei1, int E1,
                              const int* __restrict__ ei2, int E2, int N1,
                              int* __restrict__ cnt) {
    int e = blockIdx.x * blockDim.x + threadIdx.x;
    if (e < E1) {
        atomicAdd(&cnt[ei1[E1 + e]], 1);
    } else {
        int e2 = e - E1;
        if (e2 < E2) atomicAdd(&cnt[N1 + ei2[E2 + e2]], 1);
    }
}

__global__ void tile_reduce_kernel(const int* __restrict__ cnt, int* __restrict__ bsum, int n) {
    __shared__ int wtot[8];
    int b = blockIdx.x, t = threadIdx.x;
    int i0 = b * 1024 + t * 4;
    int s = 0;
    if (i0 + 3 < n) {
        int4 v = *(const int4*)(cnt + i0);
        s = v.x + v.y + v.z + v.w;
    } else {
        for (int c = 0; c < 4; c++)
            if (i0 + c < n) s += cnt[i0 + c];
    }
    int lane = t & 31, wid = t >> 5;
#pragma unroll
    for (int d = 16; d; d >>= 1) s += __shfl_xor_sync(0xffffffffu, s, d);
    if (lane == 0) wtot[wid] = s;
    __syncthreads();
    if (t == 0) {
        int tot = 0;
#pragma unroll
        for (int j = 0; j < 8; j++) tot += wtot[j];
        bsum[b] = tot;
    }
}

__global__ void scan_sums_kernel(int* __restrict__ bsum, int nb, int* __restrict__ offs_end) {
    __shared__ int w0tot;
    int t = threadIdx.x;
    int lane = t & 31, wid = t >> 5;
    int v = (t < nb) ? bsum[t] : 0;
    int x = v;
#pragma unroll
    for (int d = 1; d < 32; d <<= 1) {
        int y = __shfl_up_sync(0xffffffffu, x, d);
        if (lane >= d) x += y;
    }
    if (wid == 0 && lane == 31) w0tot = x;
    __syncthreads();
    int base = wid ? w0tot : 0;
    int excl = base + x - v;
    if (t < nb) bsum[t] = excl;
    if (t == nb - 1) *offs_end = excl + v;
}

__global__ void tile_scan_kernel(const int* __restrict__ cnt, const int* __restrict__ bsum,
                                 int* __restrict__ offs, int* __restrict__ cur, int n) {
    __shared__ int wtot[8];
    int b = blockIdx.x, t = threadIdx.x;
    int i0 = b * 1024 + t * 4;
    int v0 = 0, v1 = 0, v2 = 0, v3 = 0;
    if (i0 + 3 < n) {
        int4 vv = *(const int4*)(cnt + i0);
        v0 = vv.x; v1 = vv.y; v2 = vv.z; v3 = vv.w;
    } else {
        if (i0 < n) v0 = cnt[i0];
        if (i0 + 1 < n) v1 = cnt[i0 + 1];
        if (i0 + 2 < n) v2 = cnt[i0 + 2];
        if (i0 + 3 < n) v3 = cnt[i0 + 3];
    }
    int s = v0 + v1 + v2 + v3;
    int lane = t & 31, wid = t >> 5;
    int x = s;
#pragma unroll
    for (int d = 1; d < 32; d <<= 1) {
        int y = __shfl_up_sync(0xffffffffu, x, d);
        if (lane >= d) x += y;
    }
    if (lane == 31) wtot[wid] = x;
    __syncthreads();
    if (wid == 0 && lane < 8) {
        int y = wtot[lane];
#pragma unroll
        for (int d = 1; d < 8; d <<= 1) {
            int z = __shfl_up_sync(0xffu, y, d);
            if (lane >= d) y += z;
        }
        wtot[lane] = y;
    }
    __syncthreads();
    int wbase = wid ? wtot[wid - 1] : 0;
    int o0 = bsum[b] + wbase + (x - s);
    int o1 = o0 + v0, o2 = o1 + v1, o3 = o2 + v2;
    if (i0 + 3 < n) {
        int4 ov = make_int4(o0, o1, o2, o3);
        *(int4*)(offs + i0) = ov;
        *(int4*)(cur + i0) = ov;
    } else {
        if (i0 < n) { offs[i0] = o0; cur[i0] = o0; }
        if (i0 + 1 < n) { offs[i0 + 1] = o1; cur[i0 + 1] = o1; }
        if (i0 + 2 < n) { offs[i0 + 2] = o2; cur[i0 + 2] = o2; }
        if (i0 + 3 < n) { offs[i0 + 3] = o3; cur[i0 + 3] = o3; }
    }
}

__global__ void fill2_kernel(const int* __restrict__ ei1, int E1,
                             const int* __restrict__ ei2, int E2, int N1,
                             int* __restrict__ cur, int* __restrict__ csr) {
    int e = blockIdx.x * blockDim.x + threadIdx.x;
    if (e < E1) {
        int dst = ei1[E1 + e];
        int pos = atomicAdd(&cur[dst], 1);
        csr[pos] = ei1[e];
    } else {
        int e2 = e - E1;
        if (e2 < E2) {
            int dst = N1 + ei2[E2 + e2];
            int pos = atomicAdd(&cur[dst], 1);
            csr[pos] = N1 + ei2[e2];
        }
    }
}

// ---------------- f32x2 GEMM: O[M,128] = A[M,128] @ W[128,128]^T ----------------
// BM=128, BN=128, BK=16, 256 threads (tx=t&15, ty=t>>4), TM=8 rows, 4 col-pairs/thread.
// A tile K-MAJOR, pre-duplicated f32x2: As2T[k][row] -> per-k A reads are 4x LDS.128
// broadcasts (was 8x LDS.64). Row stride 130 u64 (STS conflict degree 2; 132 would be 4).
// Crossbar wavefronts/warp/k: 4(A) + 4(W) = 8 vs 12 before -> fma pipe gets slack.
__device__ __forceinline__ float4 ldA4(const float* A1, int M1, const float* A2, int Mtot,
                                       int gr, int col) {
    if (gr < M1) return *(const float4*)(A1 + (size_t)gr * 128 + col);
    if (gr < Mtot) return *(const float4*)(A2 + (size_t)(gr - M1) * 128 + col);
    return make_float4(0.f, 0.f, 0.f, 0.f);
}

template <bool SPLIT>
__global__ void __launch_bounds__(256, 2)
gemm_kernel(const float* __restrict__ A1, int M1, const float* __restrict__ A2, int Mtot,
            const float* __restrict__ W0, const float* __restrict__ W1,
            float* __restrict__ O0, float* __restrict__ O1) {
    __shared__ __align__(16) unsigned long long As2T[16][130];  // [k][row] duplicated pairs
    __shared__ __align__(16) float Ws[16][132];
    int t = threadIdx.x;
    int tx = t & 15, ty = t >> 4;
    int row0 = blockIdx.x * 128;
    int rr = t >> 2;              // 0..63 (two row-iters cover 128)
    int kq = (t & 3) << 2;        // 0,4,8,12

    const float* Wsel = nullptr;
    float* Osel = nullptr;
    if (!SPLIT) {
        Wsel = blockIdx.y ? W1 : W0;
        Osel = blockIdx.y ? O1 : O0;
    }

    unsigned long long acc[8][4];
#pragma unroll
    for (int i = 0; i < 8; i++)
#pragma unroll
        for (int j = 0; j < 4; j++) acc[i][j] = 0ull;

    float4 pa[2], pw[2];
    // prefetch chunk 0
#pragma unroll
    for (int i = 0; i < 2; i++) pa[i] = ldA4(A1, M1, A2, Mtot, row0 + rr + 64 * i, kq);
#pragma unroll
    for (int i = 0; i < 2; i++) {
        int n = rr + 64 * i;
        const float* wp = SPLIT ? (n < 64 ? W0 + (size_t)n * 128 : W1 + (size_t)(n - 64) * 128)
                                : Wsel + (size_t)n * 128;
        pw[i] = *(const float4*)(wp + kq);
    }

    for (int c = 0; c < 8; c++) {
        __syncthreads();
#pragma unroll
        for (int i = 0; i < 2; i++) {
            int row = rr + 64 * i;
            As2T[kq + 0][row] = dup2(pa[i].x);
            As2T[kq + 1][row] = dup2(pa[i].y);
            As2T[kq + 2][row] = dup2(pa[i].z);
            As2T[kq + 3][row] = dup2(pa[i].w);
        }
#pragma unroll
        for (int i = 0; i < 2; i++) {
            int n = rr + 64 * i;
            Ws[kq + 0][n] = pw[i].x;
            Ws[kq + 1][n] = pw[i].y;
            Ws[kq + 2][n] = pw[i].z;
            Ws[kq + 3][n] = pw[i].w;
        }
        __syncthreads();
        if (c < 7) {
            int k0 = (c + 1) * 16;
#pragma unroll
            for (int i = 0; i < 2; i++)
                pa[i] = ldA4(A1, M1, A2, Mtot, row0 + rr + 64 * i, k0 + kq);
#pragma unroll
            for (int i = 0; i < 2; i++) {
                int n = rr + 64 * i;
                const float* wp = SPLIT
                                      ? (n < 64 ? W0 + (size_t)n * 128 : W1 + (size_t)(n - 64) * 128)
                                      : Wsel + (size_t)n * 128;
                pw[i] = *(const float4*)(wp + k0 + kq);
            }
        }
#pragma unroll 4
        for (int k = 0; k < 16; k++) {
            ulonglong2 a01 = *(const ulonglong2*)&As2T[k][ty * 8 + 0];
            ulonglong2 a23 = *(const ulonglong2*)&As2T[k][ty * 8 + 2];
            ulonglong2 a45 = *(const ulonglong2*)&As2T[k][ty * 8 + 4];
            ulonglong2 a67 = *(const ulonglong2*)&As2T[k][ty * 8 + 6];
            unsigned long long ad[8] = {a01.x, a01.y, a23.x, a23.y,
                                        a45.x, a45.y, a67.x, a67.y};
            unsigned long long b2[4];
#pragma unroll
            for (int j = 0; j < 4; j++)
                b2[j] = *(const unsigned long long*)&Ws[k][2 * tx + 32 * j];
#pragma unroll
            for (int i = 0; i < 8; i++)
#pragma unroll
                for (int j = 0; j < 4; j++) ffma2(acc[i][j], ad[i], b2[j]);
        }
    }

    // epilogue: thread owns column pairs (2*tx + 32*j)
#pragma unroll
    for (int i = 0; i < 8; i++) {
        int grow = row0 + ty * 8 + i;
        if (grow < Mtot) {
#pragma unroll
            for (int j = 0; j < 4; j++) {
                int col = 2 * tx + 32 * j;
                if (SPLIT) {
                    float* Ob = (j < 2) ? O0 : O1;
                    int cc = (j < 2) ? col : col - 64;
                    *(unsigned long long*)(Ob + (size_t)grow * 64 + cc) = acc[i][j];
                } else {
                    *(unsigned long long*)(Osel + (size_t)grow * 128 + col) = acc[i][j];
                }
            }
        }
    }
}

// ---------------- fused mean aggregation + residual + bias + relu ----------------
template <int F>
__global__ void agg_fuse_kernel(const float* __restrict__ z, const float* __restrict__ rres,
                                const float* __restrict__ bias, const int* __restrict__ offs,
                                const int* __restrict__ csr, float* __restrict__ out, int M) {
    constexpr int LPN = F / 4;
    int tid = blockIdx.x * blockDim.x + threadIdx.x;
    int g = tid / LPN;
    int lane = tid % LPN;
    if (g >= M) return;
    int s = offs[g], e = offs[g + 1];
    float4 a0 = make_float4(0.f, 0.f, 0.f, 0.f);
    float4 a1 = make_float4(0.f, 0.f, 0.f, 0.f);
    int i = s;
    for (; i + 2 <= e; i += 2) {
        int s0 = csr[i], s1 = csr[i + 1];
        float4 v0 = *(const float4*)(z + (size_t)s0 * F + lane * 4);
        float4 v1 = *(const float4*)(z + (size_t)s1 * F + lane * 4);
        a0.x += v0.x; a0.y += v0.y; a0.z += v0.z; a0.w += v0.w;
        a1.x += v1.x; a1.y += v1.y; a1.z += v1.z; a1.w += v1.w;
    }
    if (i < e) {
        int s0 = csr[i];
        float4 v0 = *(const float4*)(z + (size_t)s0 * F + lane * 4);
        a0.x += v0.x; a0.y += v0.y; a0.z += v0.z; a0.w += v0.w;
    }
    float inv = 1.f / fmaxf((float)(e - s), 1.f);
    float4 rv = *(const float4*)(rres + (size_t)g * F + lane * 4);
    float4 bv = *(const float4*)(bias + lane * 4);
    float4 o;
    o.x = fmaxf((a0.x + a1.x) * inv + rv.x + bv.x, 0.f);
    o.y = fmaxf((a0.y + a1.y) * inv + rv.y + bv.y, 0.f);
    o.z = fmaxf((a0.z + a1.z) * inv + rv.z + bv.z, 0.f);
    o.w = fmaxf((a0.w + a1.w) * inv + rv.w + bv.w, 0.f);
    *(float4*)(out + (size_t)g * F + lane * 4) = o;
}

// ---------------- sort key per node ----------------
__global__ void key_kernel(const float* __restrict__ o1, const float* __restrict__ o2last,
                           unsigned long long* __restrict__ codes, int n) {
    int i = blockIdx.x * blockDim.x + threadIdx.x;
    if (i >= n) return;
    const float* r = o1 + (size_t)i * 64;
    float a2 = 0.f, dot = 0.f, b2 = 0.f;
#pragma unroll 8
    for (int d = 0; d < 64; d++) {
        float v = r[d], w = o2last[d];
        a2 += v * v;
        dot += v * w;
        b2 += w * w;
    }
    float key = a2 + b2 - 2.f * dot;
    unsigned u = __float_as_uint(key);
    u = (u & 0x80000000u) ? ~u : (u | 0x80000000u);
    codes[i] = ((unsigned long long)(~u) << 32) | (unsigned)i;
}

__device__ __forceinline__ unsigned long long umin64(unsigned long long a, unsigned long long b) {
    return a < b ? a : b;
}

__global__ void topk_kernel(const unsigned long long* __restrict__ codes,
                            int* __restrict__ sel, int npg) {
    __shared__ unsigned long long s[NPGC];
    __shared__ unsigned long long wmin[16];
    int b = blockIdx.x, t = threadIdx.x;
    int lane = t & 31, wid = t >> 5;
    for (int i = t; i < npg; i += 512) s[i] = codes[b * npg + i];
    __syncthreads();
    for (int k = 0; k < TOPK; k++) {
        unsigned long long m = ~0ull;
        for (int i = t; i < npg; i += 512) m = umin64(m, s[i]);
#pragma unroll
        for (int d = 16; d; d >>= 1) m = umin64(m, __shfl_xor_sync(0xffffffffu, m, d));
        if (lane == 0) wmin[wid] = m;
        __syncthreads();
        if (t == 0) {
            unsigned long long bb = wmin[0];
#pragma unroll
            for (int j = 1; j < 16; j++) bb = umin64(bb, wmin[j]);
            int gi = (int)(bb & 0xffffffffu);
            sel[b * TOPK + k] = gi;
            s[gi - b * npg] = ~0ull;
        }
        __syncthreads();
    }
}

__global__ void dist_kernel(const float* __restrict__ o1, const float* __restrict__ o2,
                            const int* __restrict__ sel, float* __restrict__ feat, int n2) {
    __shared__ float o1s[64];
    int bk = blockIdx.x;
    int t = threadIdx.x;
    int g = sel[bk];
    if (t < 64) o1s[t] = o1[(size_t)g * 64 + t];
    __syncthreads();
    if (t < n2) {
        float a2 = 0.f, b2 = 0.f, dot = 0.f;
        const float* q = o2 + (size_t)t * 64;
#pragma unroll 8
        for (int d = 0; d < 64; d++) {
            float v = o1s[d], w = q[d];
            a2 += v * v;
            b2 += w * w;
            dot += v * w;
        }
        float d2 = a2 + b2 - 2.f * dot;
        feat[bk * n2 + t] = sqrtf(fmaxf(d2, 0.f));
    }
}

__global__ void fc1_kernel(const float* __restrict__ feat, const float* __restrict__ w,
                           const float* __restrict__ bias, float* __restrict__ pre, int L) {
    __shared__ float red[256];
    int o = blockIdx.x, b = blockIdx.y, t = threadIdx.x;
    const float* f = feat + (size_t)b * L;
    const float* wr = w + (size_t)o * L;
    float acc = 0.f;
    for (int i = t; i < L; i += 256) acc += f[i] * wr[i];
    red[t] = acc;
    __syncthreads();
    for (int off = 128; off; off >>= 1) {
        if (t < off) red[t] += red[t + off];
        __syncthreads();
    }
    if (t == 0) pre[b * 128 + o] = red[0] + bias[o];
}

__device__ __forceinline__ float bsum128(float v, float* red) {
    int t = threadIdx.x;
    red[t] = v;
    __syncthreads();
#pragma unroll
    for (int off = 64; off; off >>= 1) {
        if (t < off) red[t] += red[t + off];
        __syncthreads();
    }
    float s = red[0];
    __syncthreads();
    return s;
}

__global__ void head_kernel(const float* __restrict__ pre, const float* __restrict__ g1,
                            const float* __restrict__ bb1, const float* __restrict__ w2,
                            const float* __restrict__ b2v, const float* __restrict__ g2,
                            const float* __restrict__ bb2, const float* __restrict__ w3,
                            const float* __restrict__ b3, float* __restrict__ out) {
    __shared__ float red[128];
    __shared__ float ybuf[128];
    int b = blockIdx.x, t = threadIdx.x;
    float x = pre[b * 128 + t];
    float mu = bsum128(x, red) * (1.f / 128.f);
    float d = x - mu;
    float var = bsum128(d * d, red) * (1.f / 128.f);
    float y = fmaxf(d * rsqrtf(var + LN_EPS) * g1[t] + bb1[t], 0.f);
    ybuf[t] = y;
    __syncthreads();
    float p = 0.f;
    if (t < 64) {
        const float* wr = w2 + t * 128;
#pragma unroll 8
        for (int i = 0; i < 128; i++) p += ybuf[i] * wr[i];
        p += b2v[t];
    }
    float mu2 = bsum128((t < 64) ? p : 0.f, red) * (1.f / 64.f);
    float dd = p - mu2;
    float var2 = bsum128((t < 64) ? dd * dd : 0.f, red) * (1.f / 64.f);
    float z = (t < 64) ? fmaxf(dd * rsqrtf(var2 + LN_EPS) * g2[t] + bb2[t], 0.f) : 0.f;
    float s = bsum128((t < 64) ? z * w3[t] : 0.f, red);
    if (t == 0) out[b] = 1.f / (1.f + expf(-(s + b3[0])));
}

// ---------------- launch ----------------
extern "C" void kernel_launch(void* const* d_in, const int* in_sizes, int n_in,
                              void* d_out, int out_size) {
    const float* x1 = (const float*)d_in[0];
    const int* ei1 = (const int*)d_in[1];
    const float* x2 = (const float*)d_in[3];
    const int* ei2 = (const int*)d_in[4];
    const float* w1l = (const float*)d_in[5];
    const float* b1l = (const float*)d_in[6];
    const float* w1r = (const float*)d_in[7];
    const float* w2l = (const float*)d_in[8];
    const float* b2l = (const float*)d_in[9];
    const float* w2r = (const float*)d_in[10];
    const float* fc1w = (const float*)d_in[11];
    const float* fc1b = (const float*)d_in[12];
    const float* ln1g = (const float*)d_in[13];
    const float* ln1b = (const float*)d_in[14];
    const float* fc2w = (const float*)d_in[15];
    const float* fc2b = (const float*)d_in[16];
    const float* ln2g = (const float*)d_in[17];
    const float* ln2b = (const float*)d_in[18];
    const float* fc3w = (const float*)d_in[19];
    const float* fc3b = (const float*)d_in[20];
    float* out = (float*)d_out;

    int N1 = in_sizes[0] / FIN;
    int E1 = in_sizes[1] / 2;
    int N2 = in_sizes[3] / FIN;
    int E2 = in_sizes[4] / 2;
    int Mtot = N1 + N2;
    int npg = N1 / BATCH;
    int nb = cdiv(Mtot, 1024);

    void* p;
    float *z, *r, *h, *o, *feat, *pre1;
    int *cnt, *offs, *cur, *csr, *sel, *bsum;
    unsigned long long* codes;
    cudaGetSymbolAddress(&p, d_z);     z = (float*)p;
    cudaGetSymbolAddress(&p, d_r);     r = (float*)p;
    cudaGetSymbolAddress(&p, d_h);     h = (float*)p;
    cudaGetSymbolAddress(&p, d_o);     o = (float*)p;
    cudaGetSymbolAddress(&p, d_cnt);   cnt = (int*)p;
    cudaGetSymbolAddress(&p, d_offs);  offs = (int*)p;
    cudaGetSymbolAddress(&p, d_cur);   cur = (int*)p;
    cudaGetSymbolAddress(&p, d_csr);   csr = (int*)p;
    cudaGetSymbolAddress(&p, d_bsum);  bsum = (int*)p;
    cudaGetSymbolAddress(&p, d_codes); codes = (unsigned long long*)p;
    cudaGetSymbolAddress(&p, d_sel);   sel = (int*)p;
    cudaGetSymbolAddress(&p, d_feat);  feat = (float*)p;
    cudaGetSymbolAddress(&p, d_pre1);  pre1 = (float*)p;

    // ---- CSR build; layer-1 GEMM stays at launch slot 4 for the ncu window ----
    zero_int_kernel<<<cdiv(Mtot, 256), 256>>>(cnt, Mtot);                       // 1
    count2_kernel<<<cdiv(E1 + E2, 256), 256>>>(ei1, E1, ei2, E2, N1, cnt);      // 2
    tile_reduce_kernel<<<nb, 256>>>(cnt, bsum, Mtot);                           // 3
    gemm_kernel<false><<<dim3(cdiv(Mtot, 128), 2), 256>>>(x1, N1, x2, Mtot,     // 4 (layer-1 GEMM)
                                                          w1l, w1r, z, r);
    scan_sums_kernel<<<1, 64>>>(bsum, nb, offs + Mtot);                         // 5
    tile_scan_kernel<<<nb, 256>>>(cnt, bsum, offs, cur, Mtot);                  // 6
    fill2_kernel<<<cdiv(E1 + E2, 256), 256>>>(ei1, E1, ei2, E2, N1, cur, csr);  // 7

    // ---- layer 1 aggregation: h = relu(mean(z) + r + b1l) ----
    agg_fuse_kernel<128><<<cdiv(Mtot * 32, 256), 256>>>(z, r, b1l, offs, csr, h, Mtot);

    // ---- layer 2: z|r = h@{w2l,w2r}^T (one launch); o = relu(mean(z) + r + b2l) ----
    gemm_kernel<true><<<cdiv(Mtot, 128), 256>>>(h, Mtot, nullptr, Mtot, w2l, w2r, z, r);
    agg_fuse_kernel<64><<<cdiv(Mtot * 16, 256), 256>>>(z, r, b2l, offs, csr, o, Mtot);

    // ---- key + top-k + sparse dist + MLP head ----
    key_kernel<<<cdiv(N1, 256), 256>>>(o, o + (size_t)(Mtot - 1) * 64, codes, N1);
    topk_kernel<<<BATCH, 512>>>(codes, sel, npg);
    dist_kernel<<<BATCH * TOPK, 256>>>(o, o + (size_t)N1 * 64, sel, feat, N2);
    fc1_kernel<<<dim3(128, BATCH), 256>>>(feat, fc1w, fc1b, pre1, TOPK * N2);
    head_kernel<<<BATCH, 128>>>(pre1, ln1g, ln1b, fc2w, fc2b, ln2g, ln2b, fc3w, fc3b, out);
}

// round 13
// speedup vs baseline: 1.1050x; 1.1050x over previous
#include <cuda_runtime.h>
#include <math.h>

#define N1C 50000
#define E1C 1000000
#define N2C 199
#define E2C 4000
#define MC (N1C + N2C)
#define FIN 128
#define BATCH 10
#define NPGC 5000
#define TOPK 50
#define LN_EPS 1e-5f

static inline int cdiv(int a, int b) { return (a + b - 1) / b; }

// ---------------- scratch ----------------
__device__ float d_z[MC * 128];
__device__ float d_r[MC * 128];
__device__ float d_h[MC * 128];
__device__ float d_o[MC * 64];
__device__ int d_cnt[MC];
__device__ int d_offs[MC + 1];
__device__ int d_cur[MC];
__device__ int d_csr[E1C + E2C];
__device__ int d_bsum[128];
__device__ unsigned long long d_codes[N1C];
__device__ int d_sel[BATCH * TOPK];
__device__ float d_feat[BATCH * TOPK * N2C];
__device__ float d_pre1[BATCH * 128];

// ---------------- f32x2 helpers ----------------
__device__ __forceinline__ unsigned long long dup2(float x) {
    unsigned long long r;
    asm("mov.b64 %0, {%1, %1};" : "=l"(r) : "r"(__float_as_uint(x)));
    return r;
}
__device__ __forceinline__ void ffma2(unsigned long long& d, unsigned long long a,
                                      unsigned long long b) {
    asm("fma.rn.f32x2 %0, %1, %2, %0;" : "+l"(d) : "l"(a), "l"(b));
}

// ---------------- CSR build ----------------
__global__ void zero_int_kernel(int* p, int n) {
    int i = blockIdx.x * blockDim.x + threadIdx.x;
    if (i < n) p[i] = 0;
}

__global__ void count2_kernel(const int* __restrict__ ei1, int E1,
                              const int* __restrict__ ei2, int E2, int N1,
                              int* __restrict__ cnt) {
    int e = blockIdx.x * blockDim.x + threadIdx.x;
    if (e < E1) {
        atomicAdd(&cnt[ei1[E1 + e]], 1);
    } else {
        int e2 = e - E1;
        if (e2 < E2) atomicAdd(&cnt[N1 + ei2[E2 + e2]], 1);
    }
}

__global__ void tile_reduce_kernel(const int* __restrict__ cnt, int* __restrict__ bsum, int n) {
    __shared__ int wtot[8];
    int b = blockIdx.x, t = threadIdx.x;
    int i0 = b * 1024 + t * 4;
    int s = 0;
    if (i0 + 3 < n) {
        int4 v = *(const int4*)(cnt + i0);
        s = v.x + v.y + v.z + v.w;
    } else {
        for (int c = 0; c < 4; c++)
            if (i0 + c < n) s += cnt[i0 + c];
    }
    int lane = t & 31, wid = t >> 5;
#pragma unroll
    for (int d = 16; d; d >>= 1) s += __shfl_xor_sync(0xffffffffu, s, d);
    if (lane == 0) wtot[wid] = s;
    __syncthreads();
    if (t == 0) {
        int tot = 0;
#pragma unroll
        for (int j = 0; j < 8; j++) tot += wtot[j];
        bsum[b] = tot;
    }
}

__global__ void scan_sums_kernel(int* __restrict__ bsum, int nb, int* __restrict__ offs_end) {
    __shared__ int w0tot;
    int t = threadIdx.x;
    int lane = t & 31, wid = t >> 5;
    int v = (t < nb) ? bsum[t] : 0;
    int x = v;
#pragma unroll
    for (int d = 1; d < 32; d <<= 1) {
        int y = __shfl_up_sync(0xffffffffu, x, d);
        if (lane >= d) x += y;
    }
    if (wid == 0 && lane == 31) w0tot = x;
    __syncthreads();
    int base = wid ? w0tot : 0;
    int excl = base + x - v;
    if (t < nb) bsum[t] = excl;
    if (t == nb - 1) *offs_end = excl + v;
}

__global__ void tile_scan_kernel(const int* __restrict__ cnt, const int* __restrict__ bsum,
                                 int* __restrict__ offs, int* __restrict__ cur, int n) {
    __shared__ int wtot[8];
    int b = blockIdx.x, t = threadIdx.x;
    int i0 = b * 1024 + t * 4;
    int v0 = 0, v1 = 0, v2 = 0, v3 = 0;
    if (i0 + 3 < n) {
        int4 vv = *(const int4*)(cnt + i0);
        v0 = vv.x; v1 = vv.y; v2 = vv.z; v3 = vv.w;
    } else {
        if (i0 < n) v0 = cnt[i0];
        if (i0 + 1 < n) v1 = cnt[i0 + 1];
        if (i0 + 2 < n) v2 = cnt[i0 + 2];
        if (i0 + 3 < n) v3 = cnt[i0 + 3];
    }
    int s = v0 + v1 + v2 + v3;
    int lane = t & 31, wid = t >> 5;
    int x = s;
#pragma unroll
    for (int d = 1; d < 32; d <<= 1) {
        int y = __shfl_up_sync(0xffffffffu, x, d);
        if (lane >= d) x += y;
    }
    if (lane == 31) wtot[wid] = x;
    __syncthreads();
    if (wid == 0 && lane < 8) {
        int y = wtot[lane];
#pragma unroll
        for (int d = 1; d < 8; d <<= 1) {
            int z = __shfl_up_sync(0xffu, y, d);
            if (lane >= d) y += z;
        }
        wtot[lane] = y;
    }
    __syncthreads();
    int wbase = wid ? wtot[wid - 1] : 0;
    int o0 = bsum[b] + wbase + (x - s);
    int o1 = o0 + v0, o2 = o1 + v1, o3 = o2 + v2;
    if (i0 + 3 < n) {
        int4 ov = make_int4(o0, o1, o2, o3);
        *(int4*)(offs + i0) = ov;
        *(int4*)(cur + i0) = ov;
    } else {
        if (i0 < n) { offs[i0] = o0; cur[i0] = o0; }
        if (i0 + 1 < n) { offs[i0 + 1] = o1; cur[i0 + 1] = o1; }
        if (i0 + 2 < n) { offs[i0 + 2] = o2; cur[i0 + 2] = o2; }
        if (i0 + 3 < n) { offs[i0 + 3] = o3; cur[i0 + 3] = o3; }
    }
}

__global__ void fill2_kernel(const int* __restrict__ ei1, int E1,
                             const int* __restrict__ ei2, int E2, int N1,
                             int* __restrict__ cur, int* __restrict__ csr) {
    int e = blockIdx.x * blockDim.x + threadIdx.x;
    if (e < E1) {
        int dst = ei1[E1 + e];
        int pos = atomicAdd(&cur[dst], 1);
        csr[pos] = ei1[e];
    } else {
        int e2 = e - E1;
        if (e2 < E2) {
            int dst = N1 + ei2[E2 + e2];
            int pos = atomicAdd(&cur[dst], 1);
            csr[pos] = N1 + ei2[e2];
        }
    }
}

// ---------------- f32x2 GEMM (R10 best-known config, unchanged) ----------------
// BM=128, BN=128, BK=16, 256 threads (tx=t&15, ty=t>>4), TM=8 rows, 4 col-pairs/thread.
// A in smem pre-duplicated as f32x2 pairs, row-major As2[row][k], stride 17 u64.
__device__ __forceinline__ float4 ldA4(const float* A1, int M1, const float* A2, int Mtot,
                                       int gr, int col) {
    if (gr < M1) return *(const float4*)(A1 + (size_t)gr * 128 + col);
    if (gr < Mtot) return *(const float4*)(A2 + (size_t)(gr - M1) * 128 + col);
    return make_float4(0.f, 0.f, 0.f, 0.f);
}

template <bool SPLIT>
__global__ void __launch_bounds__(256, 2)
gemm_kernel(const float* __restrict__ A1, int M1, const float* __restrict__ A2, int Mtot,
            const float* __restrict__ W0, const float* __restrict__ W1,
            float* __restrict__ O0, float* __restrict__ O1) {
    __shared__ __align__(16) unsigned long long As2[128][17];
    __shared__ __align__(16) float Ws[16][132];
    int t = threadIdx.x;
    int tx = t & 15, ty = t >> 4;
    int row0 = blockIdx.x * 128;
    int rr = t >> 2;
    int kq = (t & 3) << 2;

    const float* Wsel = nullptr;
    float* Osel = nullptr;
    if (!SPLIT) {
        Wsel = blockIdx.y ? W1 : W0;
        Osel = blockIdx.y ? O1 : O0;
    }

    unsigned long long acc[8][4];
#pragma unroll
    for (int i = 0; i < 8; i++)
#pragma unroll
        for (int j = 0; j < 4; j++) acc[i][j] = 0ull;

    float4 pa[2], pw[2];
#pragma unroll
    for (int i = 0; i < 2; i++) pa[i] = ldA4(A1, M1, A2, Mtot, row0 + rr + 64 * i, kq);
#pragma unroll
    for (int i = 0; i < 2; i++) {
        int n = rr + 64 * i;
        const float* wp = SPLIT ? (n < 64 ? W0 + (size_t)n * 128 : W1 + (size_t)(n - 64) * 128)
                                : Wsel + (size_t)n * 128;
        pw[i] = *(const float4*)(wp + kq);
    }

    int kx = (ty & 1) << 2;

    for (int c = 0; c < 8; c++) {
        __syncthreads();
#pragma unroll
        for (int i = 0; i < 2; i++) {
            int row = rr + 64 * i;
            int kqx = kq ^ (((row >> 3) & 1) << 2);
            As2[row][kqx + 0] = dup2(pa[i].x);
            As2[row][kqx + 1] = dup2(pa[i].y);
            As2[row][kqx + 2] = dup2(pa[i].z);
            As2[row][kqx + 3] = dup2(pa[i].w);
        }
#pragma unroll
        for (int i = 0; i < 2; i++) {
            int n = rr + 64 * i;
            Ws[kq + 0][n] = pw[i].x;
            Ws[kq + 1][n] = pw[i].y;
            Ws[kq + 2][n] = pw[i].z;
            Ws[kq + 3][n] = pw[i].w;
        }
        __syncthreads();
        if (c < 7) {
            int k0 = (c + 1) * 16;
#pragma unroll
            for (int i = 0; i < 2; i++)
                pa[i] = ldA4(A1, M1, A2, Mtot, row0 + rr + 64 * i, k0 + kq);
#pragma unroll
            for (int i = 0; i < 2; i++) {
                int n = rr + 64 * i;
                const float* wp = SPLIT
                                      ? (n < 64 ? W0 + (size_t)n * 128 : W1 + (size_t)(n - 64) * 128)
                                      : Wsel + (size_t)n * 128;
                pw[i] = *(const float4*)(wp + k0 + kq);
            }
        }
#pragma unroll 4
        for (int k = 0; k < 16; k++) {
            unsigned long long ad[8];
#pragma unroll
            for (int i = 0; i < 8; i++) ad[i] = As2[ty * 8 + i][k ^ kx];
            unsigned long long b2[4];
#pragma unroll
            for (int j = 0; j < 4; j++)
                b2[j] = *(const unsigned long long*)&Ws[k][2 * tx + 32 * j];
#pragma unroll
            for (int i = 0; i < 8; i++)
#pragma unroll
                for (int j = 0; j < 4; j++) ffma2(acc[i][j], ad[i], b2[j]);
        }
    }

#pragma unroll
    for (int i = 0; i < 8; i++) {
        int grow = row0 + ty * 8 + i;
        if (grow < Mtot) {
#pragma unroll
            for (int j = 0; j < 4; j++) {
                int col = 2 * tx + 32 * j;
                if (SPLIT) {
                    float* Ob = (j < 2) ? O0 : O1;
                    int cc = (j < 2) ? col : col - 64;
                    *(unsigned long long*)(Ob + (size_t)grow * 64 + cc) = acc[i][j];
                } else {
                    *(unsigned long long*)(Osel + (size_t)grow * 128 + col) = acc[i][j];
                }
            }
        }
    }
}

// ---------------- fused mean aggregation + residual + bias + relu ----------------
template <int F>
__global__ void agg_fuse_kernel(const float* __restrict__ z, const float* __restrict__ rres,
                                const float* __restrict__ bias, const int* __restrict__ offs,
                                const int* __restrict__ csr, float* __restrict__ out, int M) {
    constexpr int LPN = F / 4;
    int tid = blockIdx.x * blockDim.x + threadIdx.x;
    int g = tid / LPN;
    int lane = tid % LPN;
    if (g >= M) return;
    int s = offs[g], e = offs[g + 1];
    float4 a0 = make_float4(0.f, 0.f, 0.f, 0.f);
    float4 a1 = make_float4(0.f, 0.f, 0.f, 0.f);
    int i = s;
    for (; i + 2 <= e; i += 2) {
        int s0 = csr[i], s1 = csr[i + 1];
        float4 v0 = *(const float4*)(z + (size_t)s0 * F + lane * 4);
        float4 v1 = *(const float4*)(z + (size_t)s1 * F + lane * 4);
        a0.x += v0.x; a0.y += v0.y; a0.z += v0.z; a0.w += v0.w;
        a1.x += v1.x; a1.y += v1.y; a1.z += v1.z; a1.w += v1.w;
    }
    if (i < e) {
        int s0 = csr[i];
        float4 v0 = *(const float4*)(z + (size_t)s0 * F + lane * 4);
        a0.x += v0.x; a0.y += v0.y; a0.z += v0.z; a0.w += v0.w;
    }
    float inv = 1.f / fmaxf((float)(e - s), 1.f);
    float4 rv = *(const float4*)(rres + (size_t)g * F + lane * 4);
    float4 bv = *(const float4*)(bias + lane * 4);
    float4 o;
    o.x = fmaxf((a0.x + a1.x) * inv + rv.x + bv.x, 0.f);
    o.y = fmaxf((a0.y + a1.y) * inv + rv.y + bv.y, 0.f);
    o.z = fmaxf((a0.z + a1.z) * inv + rv.z + bv.z, 0.f);
    o.w = fmaxf((a0.w + a1.w) * inv + rv.w + bv.w, 0.f);
    *(float4*)(out + (size_t)g * F + lane * 4) = o;
}

// ---------------- sort key per node ----------------
__global__ void key_kernel(const float* __restrict__ o1, const float* __restrict__ o2last,
                           unsigned long long* __restrict__ codes, int n) {
    int i = blockIdx.x * blockDim.x + threadIdx.x;
    if (i >= n) return;
    const float* r = o1 + (size_t)i * 64;
    float a2 = 0.f, dot = 0.f, b2 = 0.f;
#pragma unroll 8
    for (int d = 0; d < 64; d++) {
        float v = r[d], w = o2last[d];
        a2 += v * v;
        dot += v * w;
        b2 += w * w;
    }
    float key = a2 + b2 - 2.f * dot;
    unsigned u = __float_as_uint(key);
    u = (u & 0x80000000u) ? ~u : (u | 0x80000000u);
    codes[i] = ((unsigned long long)(~u) << 32) | (unsigned)i;
}

__device__ __forceinline__ unsigned long long umin64(unsigned long long a, unsigned long long b) {
    return a < b ? a : b;
}

// ---------------- stripe-cached top-k: one block per graph ----------------
// 512 threads; thread t owns stripe {t, t+512, ...}. Stripe-min kept in register;
// per round: 2-level shuffle reduce, invalidate winner, ONLY victim rescans its stripe.
__global__ void topk_kernel(const unsigned long long* __restrict__ codes,
                            int* __restrict__ sel, int npg) {
    __shared__ unsigned long long s[NPGC];
    __shared__ unsigned long long wmin[16];
    __shared__ int victim;
    int b = blockIdx.x, t = threadIdx.x;
    int lane = t & 31, wid = t >> 5;
    for (int i = t; i < npg; i += 512) s[i] = codes[b * npg + i];
    __syncthreads();
    // initial stripe min
    unsigned long long m = ~0ull;
    for (int i = t; i < npg; i += 512) m = umin64(m, s[i]);
    for (int k = 0; k < TOPK; k++) {
        unsigned long long wm = m;
#pragma unroll
        for (int d = 16; d; d >>= 1) wm = umin64(wm, __shfl_xor_sync(0xffffffffu, wm, d));
        if (lane == 0) wmin[wid] = wm;
        __syncthreads();
        if (wid == 0) {
            unsigned long long bb = (lane < 16) ? wmin[lane] : ~0ull;
#pragma unroll
            for (int d = 8; d; d >>= 1) bb = umin64(bb, __shfl_xor_sync(0xffffffffu, bb, d));
            if (lane == 0) {
                int gi = (int)(bb & 0xffffffffu);
                sel[b * TOPK + k] = gi;
                int li = gi - b * npg;
                s[li] = ~0ull;
                victim = li & 511;  // stripe owner (stride-512 ownership)
            }
        }
        __syncthreads();
        if (t == victim) {
            m = ~0ull;
            for (int i = t; i < npg; i += 512) m = umin64(m, s[i]);
        }
        __syncthreads();
    }
}

__global__ void dist_kernel(const float* __restrict__ o1, const float* __restrict__ o2,
                            const int* __restrict__ sel, float* __restrict__ feat, int n2) {
    __shared__ float o1s[64];
    int bk = blockIdx.x;
    int t = threadIdx.x;
    int g = sel[bk];
    if (t < 64) o1s[t] = o1[(size_t)g * 64 + t];
    __syncthreads();
    if (t < n2) {
        float a2 = 0.f, b2 = 0.f, dot = 0.f;
        const float* q = o2 + (size_t)t * 64;
#pragma unroll 8
        for (int d = 0; d < 64; d++) {
            float v = o1s[d], w = q[d];
            a2 += v * v;
            b2 += w * w;
            dot += v * w;
        }
        float d2 = a2 + b2 - 2.f * dot;
        feat[bk * n2 + t] = sqrtf(fmaxf(d2, 0.f));
    }
}

__global__ void fc1_kernel(const float* __restrict__ feat, const float* __restrict__ w,
                           const float* __restrict__ bias, float* __restrict__ pre, int L) {
    __shared__ float red[256];
    int o = blockIdx.x, b = blockIdx.y, t = threadIdx.x;
    const float* f = feat + (size_t)b * L;
    const float* wr = w + (size_t)o * L;
    float acc = 0.f;
    for (int i = t; i < L; i += 256) acc += f[i] * wr[i];
    red[t] = acc;
    __syncthreads();
    for (int off = 128; off; off >>= 1) {
        if (t < off) red[t] += red[t + off];
        __syncthreads();
    }
    if (t == 0) pre[b * 128 + o] = red[0] + bias[o];
}

__device__ __forceinline__ float bsum128(float v, float* red) {
    int t = threadIdx.x;
    red[t] = v;
    __syncthreads();
#pragma unroll
    for (int off = 64; off; off >>= 1) {
        if (t < off) red[t] += red[t + off];
        __syncthreads();
    }
    float s = red[0];
    __syncthreads();
    return s;
}

__global__ void head_kernel(const float* __restrict__ pre, const float* __restrict__ g1,
                            const float* __restrict__ bb1, const float* __restrict__ w2,
                            const float* __restrict__ b2v, const float* __restrict__ g2,
                            const float* __restrict__ bb2, const float* __restrict__ w3,
                            const float* __restrict__ b3, float* __restrict__ out) {
    __shared__ float red[128];
    __shared__ float ybuf[128];
    int b = blockIdx.x, t = threadIdx.x;
    float x = pre[b * 128 + t];
    float mu = bsum128(x, red) * (1.f / 128.f);
    float d = x - mu;
    float var = bsum128(d * d, red) * (1.f / 128.f);
    float y = fmaxf(d * rsqrtf(var + LN_EPS) * g1[t] + bb1[t], 0.f);
    ybuf[t] = y;
    __syncthreads();
    float p = 0.f;
    if (t < 64) {
        const float* wr = w2 + t * 128;
#pragma unroll 8
        for (int i = 0; i < 128; i++) p += ybuf[i] * wr[i];
        p += b2v[t];
    }
    float mu2 = bsum128((t < 64) ? p : 0.f, red) * (1.f / 64.f);
    float dd = p - mu2;
    float var2 = bsum128((t < 64) ? dd * dd : 0.f, red) * (1.f / 64.f);
    float z = (t < 64) ? fmaxf(dd * rsqrtf(var2 + LN_EPS) * g2[t] + bb2[t], 0.f) : 0.f;
    float s = bsum128((t < 64) ? z * w3[t] : 0.f, red);
    if (t == 0) out[b] = 1.f / (1.f + expf(-(s + b3[0])));
}

// ---------------- launch ----------------
extern "C" void kernel_launch(void* const* d_in, const int* in_sizes, int n_in,
                              void* d_out, int out_size) {
    const float* x1 = (const float*)d_in[0];
    const int* ei1 = (const int*)d_in[1];
    const float* x2 = (const float*)d_in[3];
    const int* ei2 = (const int*)d_in[4];
    const float* w1l = (const float*)d_in[5];
    const float* b1l = (const float*)d_in[6];
    const float* w1r = (const float*)d_in[7];
    const float* w2l = (const float*)d_in[8];
    const float* b2l = (const float*)d_in[9];
    const float* w2r = (const float*)d_in[10];
    const float* fc1w = (const float*)d_in[11];
    const float* fc1b = (const float*)d_in[12];
    const float* ln1g = (const float*)d_in[13];
    const float* ln1b = (const float*)d_in[14];
    const float* fc2w = (const float*)d_in[15];
    const float* fc2b = (const float*)d_in[16];
    const float* ln2g = (const float*)d_in[17];
    const float* ln2b = (const float*)d_in[18];
    const float* fc3w = (const float*)d_in[19];
    const float* fc3b = (const float*)d_in[20];
    float* out = (float*)d_out;

    int N1 = in_sizes[0] / FIN;
    int E1 = in_sizes[1] / 2;
    int N2 = in_sizes[3] / FIN;
    int E2 = in_sizes[4] / 2;
    int Mtot = N1 + N2;
    int npg = N1 / BATCH;
    int nb = cdiv(Mtot, 1024);

    void* p;
    float *z, *r, *h, *o, *feat, *pre1;
    int *cnt, *offs, *cur, *csr, *sel, *bsum;
    unsigned long long* codes;
    cudaGetSymbolAddress(&p, d_z);     z = (float*)p;
    cudaGetSymbolAddress(&p, d_r);     r = (float*)p;
    cudaGetSymbolAddress(&p, d_h);     h = (float*)p;
    cudaGetSymbolAddress(&p, d_o);     o = (float*)p;
    cudaGetSymbolAddress(&p, d_cnt);   cnt = (int*)p;
    cudaGetSymbolAddress(&p, d_offs);  offs = (int*)p;
    cudaGetSymbolAddress(&p, d_cur);   cur = (int*)p;
    cudaGetSymbolAddress(&p, d_csr);   csr = (int*)p;
    cudaGetSymbolAddress(&p, d_bsum);  bsum = (int*)p;
    cudaGetSymbolAddress(&p, d_codes); codes = (unsigned long long*)p;
    cudaGetSymbolAddress(&p, d_sel);   sel = (int*)p;
    cudaGetSymbolAddress(&p, d_feat);  feat = (float*)p;
    cudaGetSymbolAddress(&p, d_pre1);  pre1 = (float*)p;

    // ---- CSR build; layer-1 GEMM at launch slot 4 (ncu window) ----
    zero_int_kernel<<<cdiv(Mtot, 256), 256>>>(cnt, Mtot);                       // 1
    count2_kernel<<<cdiv(E1 + E2, 256), 256>>>(ei1, E1, ei2, E2, N1, cnt);      // 2
    tile_reduce_kernel<<<nb, 256>>>(cnt, bsum, Mtot);                           // 3
    gemm_kernel<false><<<dim3(cdiv(Mtot, 128), 2), 256>>>(x1, N1, x2, Mtot,     // 4 (layer-1 GEMM)
                                                          w1l, w1r, z, r);
    scan_sums_kernel<<<1, 64>>>(bsum, nb, offs + Mtot);                         // 5
    tile_scan_kernel<<<nb, 256>>>(cnt, bsum, offs, cur, Mtot);                  // 6
    fill2_kernel<<<cdiv(E1 + E2, 256), 256>>>(ei1, E1, ei2, E2, N1, cur, csr);  // 7

    // ---- layer 1 aggregation: h = relu(mean(z) + r + b1l) ----
    agg_fuse_kernel<128><<<cdiv(Mtot * 32, 256), 256>>>(z, r, b1l, offs, csr, h, Mtot);

    // ---- layer 2: z|r = h@{w2l,w2r}^T (one launch); o = relu(mean(z) + r + b2l) ----
    gemm_kernel<true><<<cdiv(Mtot, 128), 256>>>(h, Mtot, nullptr, Mtot, w2l, w2r, z, r);
    agg_fuse_kernel<64><<<cdiv(Mtot * 16, 256), 256>>>(z, r, b2l, offs, csr, o, Mtot);

    // ---- key + top-k + sparse dist + MLP head ----
    key_kernel<<<cdiv(N1, 256), 256>>>(o, o + (size_t)(Mtot - 1) * 64, codes, N1);
    topk_kernel<<<BATCH, 512>>>(codes, sel, npg);
    dist_kernel<<<BATCH * TOPK, 256>>>(o, o + (size_t)N1 * 64, sel, feat, N2);
    fc1_kernel<<<dim3(128, BATCH), 256>>>(feat, fc1w, fc1b, pre1, TOPK * N2);
    head_kernel<<<BATCH, 128>>>(pre1, ln1g, ln1b, fc2w, fc2b, ln2g, ln2b, fc3w, fc3b, out);
}

// round 14
// speedup vs baseline: 1.2000x; 1.0860x over previous
#include <cuda_runtime.h>
#include <math.h>

#define N1C 50000
#define E1C 1000000
#define N2C 199
#define E2C 4000
#define MC (N1C + N2C)
#define FIN 128
#define BATCH 10
#define NPGC 5000
#define TOPK 50
#define LN_EPS 1e-5f

static inline int cdiv(int a, int b) { return (a + b - 1) / b; }

// ---------------- scratch ----------------
__device__ float d_z[MC * 128];
__device__ float d_r[MC * 128];
__device__ float d_h[MC * 128];
__device__ float d_o[MC * 64];
__device__ int d_cnt[MC];
__device__ int d_offs[MC + 1];
__device__ int d_cur[MC];
__device__ int d_csr[E1C + E2C];
__device__ int d_bsum[128];
__device__ unsigned long long d_codes[N1C];
__device__ int d_sel[BATCH * TOPK];
__device__ float d_feat[BATCH * TOPK * N2C];
__device__ float d_pre1[BATCH * 128];

// ---------------- f32x2 helpers ----------------
__device__ __forceinline__ unsigned long long dup2(float x) {
    unsigned long long r;
    asm("mov.b64 %0, {%1, %1};" : "=l"(r) : "r"(__float_as_uint(x)));
    return r;
}
__device__ __forceinline__ void ffma2(unsigned long long& d, unsigned long long a,
                                      unsigned long long b) {
    asm("fma.rn.f32x2 %0, %1, %2, %0;" : "+l"(d) : "l"(a), "l"(b));
}

// ---------------- CSR build ----------------
__global__ void zero_int_kernel(int* p, int n) {
    int i = blockIdx.x * blockDim.x + threadIdx.x;
    if (i < n) p[i] = 0;
}

__global__ void count2_kernel(const int* __restrict__ ei1, int E1,
                              const int* __restrict__ ei2, int E2, int N1,
                              int* __restrict__ cnt) {
    int e = blockIdx.x * blockDim.x + threadIdx.x;
    if (e < E1) {
        atomicAdd(&cnt[ei1[E1 + e]], 1);
    } else {
        int e2 = e - E1;
        if (e2 < E2) atomicAdd(&cnt[N1 + ei2[E2 + e2]], 1);
    }
}

__global__ void tile_reduce_kernel(const int* __restrict__ cnt, int* __restrict__ bsum, int n) {
    __shared__ int wtot[8];
    int b = blockIdx.x, t = threadIdx.x;
    int i0 = b * 1024 + t * 4;
    int s = 0;
    if (i0 + 3 < n) {
        int4 v = *(const int4*)(cnt + i0);
        s = v.x + v.y + v.z + v.w;
    } else {
        for (int c = 0; c < 4; c++)
            if (i0 + c < n) s += cnt[i0 + c];
    }
    int lane = t & 31, wid = t >> 5;
#pragma unroll
    for (int d = 16; d; d >>= 1) s += __shfl_xor_sync(0xffffffffu, s, d);
    if (lane == 0) wtot[wid] = s;
    __syncthreads();
    if (t == 0) {
        int tot = 0;
#pragma unroll
        for (int j = 0; j < 8; j++) tot += wtot[j];
        bsum[b] = tot;
    }
}

__global__ void scan_sums_kernel(int* __restrict__ bsum, int nb, int* __restrict__ offs_end) {
    __shared__ int w0tot;
    int t = threadIdx.x;
    int lane = t & 31, wid = t >> 5;
    int v = (t < nb) ? bsum[t] : 0;
    int x = v;
#pragma unroll
    for (int d = 1; d < 32; d <<= 1) {
        int y = __shfl_up_sync(0xffffffffu, x, d);
        if (lane >= d) x += y;
    }
    if (wid == 0 && lane == 31) w0tot = x;
    __syncthreads();
    int base = wid ? w0tot : 0;
    int excl = base + x - v;
    if (t < nb) bsum[t] = excl;
    if (t == nb - 1) *offs_end = excl + v;
}

__global__ void tile_scan_kernel(const int* __restrict__ cnt, const int* __restrict__ bsum,
                                 int* __restrict__ offs, int* __restrict__ cur, int n) {
    __shared__ int wtot[8];
    int b = blockIdx.x, t = threadIdx.x;
    int i0 = b * 1024 + t * 4;
    int v0 = 0, v1 = 0, v2 = 0, v3 = 0;
    if (i0 + 3 < n) {
        int4 vv = *(const int4*)(cnt + i0);
        v0 = vv.x; v1 = vv.y; v2 = vv.z; v3 = vv.w;
    } else {
        if (i0 < n) v0 = cnt[i0];
        if (i0 + 1 < n) v1 = cnt[i0 + 1];
        if (i0 + 2 < n) v2 = cnt[i0 + 2];
        if (i0 + 3 < n) v3 = cnt[i0 + 3];
    }
    int s = v0 + v1 + v2 + v3;
    int lane = t & 31, wid = t >> 5;
    int x = s;
#pragma unroll
    for (int d = 1; d < 32; d <<= 1) {
        int y = __shfl_up_sync(0xffffffffu, x, d);
        if (lane >= d) x += y;
    }
    if (lane == 31) wtot[wid] = x;
    __syncthreads();
    if (wid == 0 && lane < 8) {
        int y = wtot[lane];
#pragma unroll
        for (int d = 1; d < 8; d <<= 1) {
            int z = __shfl_up_sync(0xffu, y, d);
            if (lane >= d) y += z;
        }
        wtot[lane] = y;
    }
    __syncthreads();
    int wbase = wid ? wtot[wid - 1] : 0;
    int o0 = bsum[b] + wbase + (x - s);
    int o1 = o0 + v0, o2 = o1 + v1, o3 = o2 + v2;
    if (i0 + 3 < n) {
        int4 ov = make_int4(o0, o1, o2, o3);
        *(int4*)(offs + i0) = ov;
        *(int4*)(cur + i0) = ov;
    } else {
        if (i0 < n) { offs[i0] = o0; cur[i0] = o0; }
        if (i0 + 1 < n) { offs[i0 + 1] = o1; cur[i0 + 1] = o1; }
        if (i0 + 2 < n) { offs[i0 + 2] = o2; cur[i0 + 2] = o2; }
        if (i0 + 3 < n) { offs[i0 + 3] = o3; cur[i0 + 3] = o3; }
    }
}

__global__ void fill2_kernel(const int* __restrict__ ei1, int E1,
                             const int* __restrict__ ei2, int E2, int N1,
                             int* __restrict__ cur, int* __restrict__ csr) {
    int e = blockIdx.x * blockDim.x + threadIdx.x;
    if (e < E1) {
        int dst = ei1[E1 + e];
        int pos = atomicAdd(&cur[dst], 1);
        csr[pos] = ei1[e];
    } else {
        int e2 = e - E1;
        if (e2 < E2) {
            int dst = N1 + ei2[E2 + e2];
            int pos = atomicAdd(&cur[dst], 1);
            csr[pos] = N1 + ei2[e2];
        }
    }
}

// ---------------- f32x2 GEMM (R10/R13 best-known config, unchanged) ----------------
__device__ __forceinline__ float4 ldA4(const float* A1, int M1, const float* A2, int Mtot,
                                       int gr, int col) {
    if (gr < M1) return *(const float4*)(A1 + (size_t)gr * 128 + col);
    if (gr < Mtot) return *(const float4*)(A2 + (size_t)(gr - M1) * 128 + col);
    return make_float4(0.f, 0.f, 0.f, 0.f);
}

template <bool SPLIT>
__global__ void __launch_bounds__(256, 2)
gemm_kernel(const float* __restrict__ A1, int M1, const float* __restrict__ A2, int Mtot,
            const float* __restrict__ W0, const float* __restrict__ W1,
            float* __restrict__ O0, float* __restrict__ O1) {
    __shared__ __align__(16) unsigned long long As2[128][17];
    __shared__ __align__(16) float Ws[16][132];
    int t = threadIdx.x;
    int tx = t & 15, ty = t >> 4;
    int row0 = blockIdx.x * 128;
    int rr = t >> 2;
    int kq = (t & 3) << 2;

    const float* Wsel = nullptr;
    float* Osel = nullptr;
    if (!SPLIT) {
        Wsel = blockIdx.y ? W1 : W0;
        Osel = blockIdx.y ? O1 : O0;
    }

    unsigned long long acc[8][4];
#pragma unroll
    for (int i = 0; i < 8; i++)
#pragma unroll
        for (int j = 0; j < 4; j++) acc[i][j] = 0ull;

    float4 pa[2], pw[2];
#pragma unroll
    for (int i = 0; i < 2; i++) pa[i] = ldA4(A1, M1, A2, Mtot, row0 + rr + 64 * i, kq);
#pragma unroll
    for (int i = 0; i < 2; i++) {
        int n = rr + 64 * i;
        const float* wp = SPLIT ? (n < 64 ? W0 + (size_t)n * 128 : W1 + (size_t)(n - 64) * 128)
                                : Wsel + (size_t)n * 128;
        pw[i] = *(const float4*)(wp + kq);
    }

    int kx = (ty & 1) << 2;

    for (int c = 0; c < 8; c++) {
        __syncthreads();
#pragma unroll
        for (int i = 0; i < 2; i++) {
            int row = rr + 64 * i;
            int kqx = kq ^ (((row >> 3) & 1) << 2);
            As2[row][kqx + 0] = dup2(pa[i].x);
            As2[row][kqx + 1] = dup2(pa[i].y);
            As2[row][kqx + 2] = dup2(pa[i].z);
            As2[row][kqx + 3] = dup2(pa[i].w);
        }
#pragma unroll
        for (int i = 0; i < 2; i++) {
            int n = rr + 64 * i;
            Ws[kq + 0][n] = pw[i].x;
            Ws[kq + 1][n] = pw[i].y;
            Ws[kq + 2][n] = pw[i].z;
            Ws[kq + 3][n] = pw[i].w;
        }
        __syncthreads();
        if (c < 7) {
            int k0 = (c + 1) * 16;
#pragma unroll
            for (int i = 0; i < 2; i++)
                pa[i] = ldA4(A1, M1, A2, Mtot, row0 + rr + 64 * i, k0 + kq);
#pragma unroll
            for (int i = 0; i < 2; i++) {
                int n = rr + 64 * i;
                const float* wp = SPLIT
                                      ? (n < 64 ? W0 + (size_t)n * 128 : W1 + (size_t)(n - 64) * 128)
                                      : Wsel + (size_t)n * 128;
                pw[i] = *(const float4*)(wp + k0 + kq);
            }
        }
#pragma unroll 4
        for (int k = 0; k < 16; k++) {
            unsigned long long ad[8];
#pragma unroll
            for (int i = 0; i < 8; i++) ad[i] = As2[ty * 8 + i][k ^ kx];
            unsigned long long b2[4];
#pragma unroll
            for (int j = 0; j < 4; j++)
                b2[j] = *(const unsigned long long*)&Ws[k][2 * tx + 32 * j];
#pragma unroll
            for (int i = 0; i < 8; i++)
#pragma unroll
                for (int j = 0; j < 4; j++) ffma2(acc[i][j], ad[i], b2[j]);
        }
    }

#pragma unroll
    for (int i = 0; i < 8; i++) {
        int grow = row0 + ty * 8 + i;
        if (grow < Mtot) {
#pragma unroll
            for (int j = 0; j < 4; j++) {
                int col = 2 * tx + 32 * j;
                if (SPLIT) {
                    float* Ob = (j < 2) ? O0 : O1;
                    int cc = (j < 2) ? col : col - 64;
                    *(unsigned long long*)(Ob + (size_t)grow * 64 + cc) = acc[i][j];
                } else {
                    *(unsigned long long*)(Osel + (size_t)grow * 128 + col) = acc[i][j];
                }
            }
        }
    }
}

// ---------------- fused mean aggregation + residual + bias + relu ----------------
// processes nodes [g0, g0+M)
template <int F>
__global__ void agg_fuse_kernel(const float* __restrict__ z, const float* __restrict__ rres,
                                const float* __restrict__ bias, const int* __restrict__ offs,
                                const int* __restrict__ csr, float* __restrict__ out,
                                int g0, int M) {
    constexpr int LPN = F / 4;
    int tid = blockIdx.x * blockDim.x + threadIdx.x;
    int g = tid / LPN;
    int lane = tid % LPN;
    if (g >= M) return;
    g += g0;
    int s = offs[g], e = offs[g + 1];
    float4 a0 = make_float4(0.f, 0.f, 0.f, 0.f);
    float4 a1 = make_float4(0.f, 0.f, 0.f, 0.f);
    int i = s;
    for (; i + 2 <= e; i += 2) {
        int s0 = csr[i], s1 = csr[i + 1];
        float4 v0 = *(const float4*)(z + (size_t)s0 * F + lane * 4);
        float4 v1 = *(const float4*)(z + (size_t)s1 * F + lane * 4);
        a0.x += v0.x; a0.y += v0.y; a0.z += v0.z; a0.w += v0.w;
        a1.x += v1.x; a1.y += v1.y; a1.z += v1.z; a1.w += v1.w;
    }
    if (i < e) {
        int s0 = csr[i];
        float4 v0 = *(const float4*)(z + (size_t)s0 * F + lane * 4);
        a0.x += v0.x; a0.y += v0.y; a0.z += v0.z; a0.w += v0.w;
    }
    float inv = 1.f / fmaxf((float)(e - s), 1.f);
    float4 rv = *(const float4*)(rres + (size_t)g * F + lane * 4);
    float4 bv = *(const float4*)(bias + lane * 4);
    float4 o;
    o.x = fmaxf((a0.x + a1.x) * inv + rv.x + bv.x, 0.f);
    o.y = fmaxf((a0.y + a1.y) * inv + rv.y + bv.y, 0.f);
    o.z = fmaxf((a0.z + a1.z) * inv + rv.z + bv.z, 0.f);
    o.w = fmaxf((a0.w + a1.w) * inv + rv.w + bv.w, 0.f);
    *(float4*)(out + (size_t)g * F + lane * 4) = o;
}

// ---------------- layer-2 aggregation fused with sort-key emission (graph-1 nodes) ----
__global__ void agg_fuse_key_kernel(const float* __restrict__ z, const float* __restrict__ rres,
                                    const float* __restrict__ bias, const int* __restrict__ offs,
                                    const int* __restrict__ csr, float* __restrict__ out, int M,
                                    const float* __restrict__ o2last,
                                    unsigned long long* __restrict__ codes) {
    constexpr int LPN = 16;  // F=64
    int tid = blockIdx.x * blockDim.x + threadIdx.x;
    int g = tid / LPN;
    int lane = tid % LPN;
    if (g >= M) return;
    int s = offs[g], e = offs[g + 1];
    float4 a0 = make_float4(0.f, 0.f, 0.f, 0.f);
    float4 a1 = make_float4(0.f, 0.f, 0.f, 0.f);
    int i = s;
    for (; i + 2 <= e; i += 2) {
        int s0 = csr[i], s1 = csr[i + 1];
        float4 v0 = *(const float4*)(z + (size_t)s0 * 64 + lane * 4);
        float4 v1 = *(const float4*)(z + (size_t)s1 * 64 + lane * 4);
        a0.x += v0.x; a0.y += v0.y; a0.z += v0.z; a0.w += v0.w;
        a1.x += v1.x; a1.y += v1.y; a1.z += v1.z; a1.w += v1.w;
    }
    if (i < e) {
        int s0 = csr[i];
        float4 v0 = *(const float4*)(z + (size_t)s0 * 64 + lane * 4);
        a0.x += v0.x; a0.y += v0.y; a0.z += v0.z; a0.w += v0.w;
    }
    float inv = 1.f / fmaxf((float)(e - s), 1.f);
    float4 rv = *(const float4*)(rres + (size_t)g * 64 + lane * 4);
    float4 bv = *(const float4*)(bias + lane * 4);
    float4 o;
    o.x = fmaxf((a0.x + a1.x) * inv + rv.x + bv.x, 0.f);
    o.y = fmaxf((a0.y + a1.y) * inv + rv.y + bv.y, 0.f);
    o.z = fmaxf((a0.z + a1.z) * inv + rv.z + bv.z, 0.f);
    o.w = fmaxf((a0.w + a1.w) * inv + rv.w + bv.w, 0.f);
    *(float4*)(out + (size_t)g * 64 + lane * 4) = o;
    // key: d2 to o2last, reduced over the node's 16 lanes (xor offsets <16 stay in-group)
    float4 w = *(const float4*)(o2last + lane * 4);
    float pa2 = o.x * o.x + o.y * o.y + o.z * o.z + o.w * o.w;
    float pdot = o.x * w.x + o.y * w.y + o.z * w.z + o.w * w.w;
    float pb2 = w.x * w.x + w.y * w.y + w.z * w.z + w.w * w.w;
#pragma unroll
    for (int d = 8; d; d >>= 1) {
        pa2 += __shfl_xor_sync(0xffffffffu, pa2, d);
        pdot += __shfl_xor_sync(0xffffffffu, pdot, d);
        pb2 += __shfl_xor_sync(0xffffffffu, pb2, d);
    }
    if (lane == 0) {
        float key = pa2 + pb2 - 2.f * pdot;
        unsigned u = __float_as_uint(key);
        u = (u & 0x80000000u) ? ~u : (u | 0x80000000u);
        codes[g] = ((unsigned long long)(~u) << 32) | (unsigned)g;
    }
}

__device__ __forceinline__ unsigned long long umin64(unsigned long long a, unsigned long long b) {
    return a < b ? a : b;
}

// ---------------- stripe-cached top-k (R13 winner, unchanged) ----------------
__global__ void topk_kernel(const unsigned long long* __restrict__ codes,
                            int* __restrict__ sel, int npg) {
    __shared__ unsigned long long s[NPGC];
    __shared__ unsigned long long wmin[16];
    __shared__ int victim;
    int b = blockIdx.x, t = threadIdx.x;
    int lane = t & 31, wid = t >> 5;
    for (int i = t; i < npg; i += 512) s[i] = codes[b * npg + i];
    __syncthreads();
    unsigned long long m = ~0ull;
    for (int i = t; i < npg; i += 512) m = umin64(m, s[i]);
    for (int k = 0; k < TOPK; k++) {
        unsigned long long wm = m;
#pragma unroll
        for (int d = 16; d; d >>= 1) wm = umin64(wm, __shfl_xor_sync(0xffffffffu, wm, d));
        if (lane == 0) wmin[wid] = wm;
        __syncthreads();
        if (wid == 0) {
            unsigned long long bb = (lane < 16) ? wmin[lane] : ~0ull;
#pragma unroll
            for (int d = 8; d; d >>= 1) bb = umin64(bb, __shfl_xor_sync(0xffffffffu, bb, d));
            if (lane == 0) {
                int gi = (int)(bb & 0xffffffffu);
                sel[b * TOPK + k] = gi;
                int li = gi - b * npg;
                s[li] = ~0ull;
                victim = li & 511;
            }
        }
        __syncthreads();
        if (t == victim) {
            m = ~0ull;
            for (int i = t; i < npg; i += 512) m = umin64(m, s[i]);
        }
        __syncthreads();
    }
}

__global__ void dist_kernel(const float* __restrict__ o1, const float* __restrict__ o2,
                            const int* __restrict__ sel, float* __restrict__ feat, int n2) {
    __shared__ float o1s[64];
    int bk = blockIdx.x;
    int t = threadIdx.x;
    int g = sel[bk];
    if (t < 64) o1s[t] = o1[(size_t)g * 64 + t];
    __syncthreads();
    if (t < n2) {
        float a2 = 0.f, b2 = 0.f, dot = 0.f;
        const float* q = o2 + (size_t)t * 64;
#pragma unroll 8
        for (int d = 0; d < 64; d++) {
            float v = o1s[d], w = q[d];
            a2 += v * v;
            b2 += w * w;
            dot += v * w;
        }
        float d2 = a2 + b2 - 2.f * dot;
        feat[bk * n2 + t] = sqrtf(fmaxf(d2, 0.f));
    }
}

__global__ void fc1_kernel(const float* __restrict__ feat, const float* __restrict__ w,
                           const float* __restrict__ bias, float* __restrict__ pre, int L) {
    __shared__ float red[256];
    int o = blockIdx.x, b = blockIdx.y, t = threadIdx.x;
    const float* f = feat + (size_t)b * L;
    const float* wr = w + (size_t)o * L;
    float acc = 0.f;
    for (int i = t; i < L; i += 256) acc += f[i] * wr[i];
    red[t] = acc;
    __syncthreads();
    for (int off = 128; off; off >>= 1) {
        if (t < off) red[t] += red[t + off];
        __syncthreads();
    }
    if (t == 0) pre[b * 128 + o] = red[0] + bias[o];
}

__device__ __forceinline__ float bsum128(float v, float* red) {
    int t = threadIdx.x;
    red[t] = v;
    __syncthreads();
#pragma unroll
    for (int off = 64; off; off >>= 1) {
        if (t < off) red[t] += red[t + off];
        __syncthreads();
    }
    float s = red[0];
    __syncthreads();
    return s;
}

__global__ void head_kernel(const float* __restrict__ pre, const float* __restrict__ g1,
                            const float* __restrict__ bb1, const float* __restrict__ w2,
                            const float* __restrict__ b2v, const float* __restrict__ g2,
                            const float* __restrict__ bb2, const float* __restrict__ w3,
                            const float* __restrict__ b3, float* __restrict__ out) {
    __shared__ float red[128];
    __shared__ float ybuf[128];
    int b = blockIdx.x, t = threadIdx.x;
    float x = pre[b * 128 + t];
    float mu = bsum128(x, red) * (1.f / 128.f);
    float d = x - mu;
    float var = bsum128(d * d, red) * (1.f / 128.f);
    float y = fmaxf(d * rsqrtf(var + LN_EPS) * g1[t] + bb1[t], 0.f);
    ybuf[t] = y;
    __syncthreads();
    float p = 0.f;
    if (t < 64) {
        const float* wr = w2 + t * 128;
#pragma unroll 8
        for (int i = 0; i < 128; i++) p += ybuf[i] * wr[i];
        p += b2v[t];
    }
    float mu2 = bsum128((t < 64) ? p : 0.f, red) * (1.f / 64.f);
    float dd = p - mu2;
    float var2 = bsum128((t < 64) ? dd * dd : 0.f, red) * (1.f / 64.f);
    float z = (t < 64) ? fmaxf(dd * rsqrtf(var2 + LN_EPS) * g2[t] + bb2[t], 0.f) : 0.f;
    float s = bsum128((t < 64) ? z * w3[t] : 0.f, red);
    if (t == 0) out[b] = 1.f / (1.f + expf(-(s + b3[0])));
}

// ---------------- launch ----------------
extern "C" void kernel_launch(void* const* d_in, const int* in_sizes, int n_in,
                              void* d_out, int out_size) {
    const float* x1 = (const float*)d_in[0];
    const int* ei1 = (const int*)d_in[1];
    const float* x2 = (const float*)d_in[3];
    const int* ei2 = (const int*)d_in[4];
    const float* w1l = (const float*)d_in[5];
    const float* b1l = (const float*)d_in[6];
    const float* w1r = (const float*)d_in[7];
    const float* w2l = (const float*)d_in[8];
    const float* b2l = (const float*)d_in[9];
    const float* w2r = (const float*)d_in[10];
    const float* fc1w = (const float*)d_in[11];
    const float* fc1b = (const float*)d_in[12];
    const float* ln1g = (const float*)d_in[13];
    const float* ln1b = (const float*)d_in[14];
    const float* fc2w = (const float*)d_in[15];
    const float* fc2b = (const float*)d_in[16];
    const float* ln2g = (const float*)d_in[17];
    const float* ln2b = (const float*)d_in[18];
    const float* fc3w = (const float*)d_in[19];
    const float* fc3b = (const float*)d_in[20];
    float* out = (float*)d_out;

    int N1 = in_sizes[0] / FIN;
    int E1 = in_sizes[1] / 2;
    int N2 = in_sizes[3] / FIN;
    int E2 = in_sizes[4] / 2;
    int Mtot = N1 + N2;
    int npg = N1 / BATCH;
    int nb = cdiv(Mtot, 1024);

    void* p;
    float *z, *r, *h, *o, *feat, *pre1;
    int *cnt, *offs, *cur, *csr, *sel, *bsum;
    unsigned long long* codes;
    cudaGetSymbolAddress(&p, d_z);     z = (float*)p;
    cudaGetSymbolAddress(&p, d_r);     r = (float*)p;
    cudaGetSymbolAddress(&p, d_h);     h = (float*)p;
    cudaGetSymbolAddress(&p, d_o);     o = (float*)p;
    cudaGetSymbolAddress(&p, d_cnt);   cnt = (int*)p;
    cudaGetSymbolAddress(&p, d_offs);  offs = (int*)p;
    cudaGetSymbolAddress(&p, d_cur);   cur = (int*)p;
    cudaGetSymbolAddress(&p, d_csr);   csr = (int*)p;
    cudaGetSymbolAddress(&p, d_bsum);  bsum = (int*)p;
    cudaGetSymbolAddress(&p, d_codes); codes = (unsigned long long*)p;
    cudaGetSymbolAddress(&p, d_sel);   sel = (int*)p;
    cudaGetSymbolAddress(&p, d_feat);  feat = (float*)p;
    cudaGetSymbolAddress(&p, d_pre1);  pre1 = (float*)p;

    // ---- fork: CSR build on side stream, overlapped with layer-1 GEMM ----
    cudaStream_t s2;
    cudaStreamCreateWithFlags(&s2, cudaStreamNonBlocking);
    cudaEvent_t evFork, evCsr;
    cudaEventCreateWithFlags(&evFork, cudaEventDisableTiming);
    cudaEventCreateWithFlags(&evCsr, cudaEventDisableTiming);
    cudaEventRecord(evFork, 0);
    cudaStreamWaitEvent(s2, evFork, 0);

    zero_int_kernel<<<cdiv(Mtot, 256), 256, 0, s2>>>(cnt, Mtot);
    count2_kernel<<<cdiv(E1 + E2, 256), 256, 0, s2>>>(ei1, E1, ei2, E2, N1, cnt);
    tile_reduce_kernel<<<nb, 256, 0, s2>>>(cnt, bsum, Mtot);
    scan_sums_kernel<<<1, 64, 0, s2>>>(bsum, nb, offs + Mtot);
    tile_scan_kernel<<<nb, 256, 0, s2>>>(cnt, bsum, offs, cur, Mtot);
    fill2_kernel<<<cdiv(E1 + E2, 256), 256, 0, s2>>>(ei1, E1, ei2, E2, N1, cur, csr);
    cudaEventRecord(evCsr, s2);

    // layer-1 GEMM on main stream (93 us; hides the CSR chain)
    gemm_kernel<false><<<dim3(cdiv(Mtot, 128), 2), 256>>>(x1, N1, x2, Mtot, w1l, w1r, z, r);

    // join: agg1 needs GEMM1 (z,r) + CSR
    cudaStreamWaitEvent(0, evCsr, 0);

    // ---- layer 1 aggregation: h = relu(mean(z) + r + b1l) ----
    agg_fuse_kernel<128><<<cdiv(Mtot * 32, 256), 256>>>(z, r, b1l, offs, csr, h, 0, Mtot);

    // ---- layer 2: z|r = h@{w2l,w2r}^T ----
    gemm_kernel<true><<<cdiv(Mtot, 128), 256>>>(h, Mtot, nullptr, Mtot, w2l, w2r, z, r);
    // graph-2 nodes first (tiny) -> produces o2last, then graph-1 nodes fused with key emission
    agg_fuse_kernel<64><<<cdiv(N2 * 16, 256) + 1, 256>>>(z, r, b2l, offs, csr, o, N1, N2);
    agg_fuse_key_kernel<<<cdiv(N1 * 16, 256), 256>>>(z, r, b2l, offs, csr, o, N1,
                                                     o + (size_t)(Mtot - 1) * 64, codes);

    // ---- top-k + sparse dist + MLP head ----
    topk_kernel<<<BATCH, 512>>>(codes, sel, npg);
    dist_kernel<<<BATCH * TOPK, 256>>>(o, o + (size_t)N1 * 64, sel, feat, N2);
    fc1_kernel<<<dim3(128, BATCH), 256>>>(feat, fc1w, fc1b, pre1, TOPK * N2);
    head_kernel<<<BATCH, 128>>>(pre1, ln1g, ln1b, fc2w, fc2b, ln2g, ln2b, fc3w, fc3b, out);
}